// round 4
// baseline (speedup 1.0000x reference)
#include <cuda_runtime.h>
#include <cstdint>

#define S 1024
#define D 64
#define NPOS 64
#define BH 48
#define KC 64
#define TQ 32
#define KP_COLS 384            // precomputed keyproj tail columns
#define KP_START (S - KP_COLS) // 640
#define NPOS_M1 63.0f

// Scratch (allowed: __device__ globals)
__device__ float g_keypT[(size_t)BH * D * S];    // [bh][d][s] (only s >= KP_START filled)

// ---- packed f32x2 helpers ---------------------------------------------------
__device__ __forceinline__ unsigned long long pack2(float a) {
    unsigned long long r;
    asm("mov.b64 %0, {%1, %1};" : "=l"(r) : "f"(a));
    return r;
}
__device__ __forceinline__ void fma2(unsigned long long& d,
                                     unsigned long long a, unsigned long long b) {
    asm("fma.rn.f32x2 %0, %1, %2, %0;" : "+l"(d) : "l"(a), "l"(b));
}
__device__ __forceinline__ float2 unpack2(unsigned long long v) {
    float2 f;
    asm("mov.b64 {%0, %1}, %2;" : "=f"(f.x), "=f"(f.y) : "l"(v));
    return f;
}

// ---------------------------------------------------------------------------
// keyproj tail: g_keypT[bh][d][s] = sum_k key[bh][s][k]*w_k[k][d], s in tail
// ---------------------------------------------------------------------------
__global__ __launch_bounds__(256) void keyproj_kernel(
    const float* __restrict__ key, const float* __restrict__ wk)
{
    __shared__ float w_s[64 * 64];
    __shared__ float in_s[64 * 68];
    const int bh  = blockIdx.x;
    const int s0  = KP_START + blockIdx.y * 64;
    const int tid = threadIdx.x;

    for (int idx = tid; idx < 1024; idx += 256)
        ((float4*)w_s)[idx] = ((const float4*)wk)[idx];
    {
        const float* kp = key + ((size_t)bh * S + s0) * D;
        for (int idx = tid; idx < 64 * 16; idx += 256) {
            int r = idx >> 4, c = idx & 15;
            float4 v = ((const float4*)(kp + (size_t)r * D))[c];
            *(float4*)&in_s[r * 68 + c * 4] = v;
        }
    }
    __syncthreads();

    const int ox = tid & 15;   // d-group
    const int sy = tid >> 4;   // s-group

    unsigned long long acc[4][2];
#pragma unroll
    for (int i = 0; i < 4; i++) { acc[i][0] = 0ull; acc[i][1] = 0ull; }

#pragma unroll
    for (int k4 = 0; k4 < 16; k4++) {
        float4 av[4];
#pragma unroll
        for (int i = 0; i < 4; i++)
            av[i] = *(const float4*)&in_s[(4 * sy + i) * 68 + 4 * k4];
#pragma unroll
        for (int t = 0; t < 4; t++) {
            ulonglong2 wv = *(const ulonglong2*)&w_s[(4 * k4 + t) * 64 + 4 * ox];
#pragma unroll
            for (int i = 0; i < 4; i++) {
                float a = (t == 0) ? av[i].x : (t == 1) ? av[i].y : (t == 2) ? av[i].z : av[i].w;
                unsigned long long a2 = pack2(a);
                fma2(acc[i][0], a2, wv.x);
                fma2(acc[i][1], a2, wv.y);
            }
        }
    }

    float a_[4][4];
#pragma unroll
    for (int i = 0; i < 4; i++) {
        float2 u0 = unpack2(acc[i][0]), u1 = unpack2(acc[i][1]);
        a_[i][0] = u0.x; a_[i][1] = u0.y; a_[i][2] = u1.x; a_[i][3] = u1.y;
    }
#pragma unroll
    for (int j = 0; j < 4; j++) {
        float4 o = make_float4(a_[0][j], a_[1][j], a_[2][j], a_[3][j]);
        *(float4*)&g_keypT[((size_t)bh * D + 4 * ox + j) * S + s0 + 4 * sy] = o;
    }
}

// ---------------------------------------------------------------------------
// Main fused kernel. TQ=32 rows/block, 8 warps (4 rows each), KC=64 chunks,
// lane owns 2 adjacent columns. Double-buffered kpT, 1 barrier per chunk.
// smem floats: qs2[4096] | li[2048] | kpT[2*4096]  => 14336 floats = 57344 B
// ---------------------------------------------------------------------------
#define QS2_F   0
#define LI_F    4096
#define KPT_F   6144
#define SMEM_FLOATS 14336
#define SMEM_BYTES (SMEM_FLOATS * 4)

__device__ __forceinline__ float interp_li(float pos, const float* __restrict__ lir) {
    pos = fminf(pos, NPOS_M1);
    float pf = floorf(pos);
    int ip = (int)pf;
    float w = pos - pf;
    int ic = (ip < 63) ? ip + 1 : 63;
    float lf = lir[ip], lc = lir[ic];
    return fmaf(w, lc - lf, lf);
}

__device__ __forceinline__ void stage_chunk(
    float* __restrict__ kbuf, int bh, int jc, int tid,
    const float* __restrict__ key, const float* __restrict__ wk)
{
    if (jc >= KP_START) {
        // g_keypT is [bh][d][S]; copy 64 cols per d row. 1024 float4 / 256 thr.
#pragma unroll
        for (int u = 0; u < 4; u++) {
            int idx = tid + u * 256;
            int d = idx >> 4, c4 = idx & 15;
            float4 v = ((const float4*)(g_keypT + ((size_t)bh * D + d) * S + jc))[c4];
            *(float4*)&kbuf[d * KC + c4 * 4] = v;
        }
    } else {
        // correctness fallback (statistically never taken)
        for (int idx = tid; idx < D * KC; idx += 256) {
            int d = idx >> 6, c = idx & 63;
            const float* krow = key + ((size_t)bh * S + jc + c) * D;
            float s = 0.f;
#pragma unroll
            for (int k = 0; k < D; k++) s += krow[k] * wk[k * D + d];
            kbuf[d * KC + c] = s;
        }
    }
}

__global__ __launch_bounds__(256, 4) void cope_kernel(
    const float* __restrict__ query, const float* __restrict__ key,
    const float* __restrict__ pe, const float* __restrict__ wk,
    const int* __restrict__ flag, float* __restrict__ out)
{
    extern __shared__ float sm[];
    unsigned long long* qs2u = (unsigned long long*)(sm + QS2_F); // [32][64] dup pairs
    float* li   = sm + LI_F;                                      // [32][64]
    float* kpT  = sm + KPT_F;                                     // 2 x [64][64]
    float* peS  = sm + KPT_F;                                     // staged pe (pre-loop)
    float* liin = sm + KPT_F + 4096;                              // staged li inputs

    const int bh   = blockIdx.y;
    const int q0   = blockIdx.x * TQ;
    const int tid  = threadIdx.x;
    const int lane = tid & 31;
    const int wrp  = tid >> 5;

    // ---- stage: qs2 (query*0.125 dup), liin, pe ------------------------------
    const float* lisrc = (flag[0] != 0) ? query : key;
#pragma unroll
    for (int u = 0; u < 2; u++) {
        int idx = tid + u * 256;            // 512 float4 groups
        int r = idx >> 4, c = idx & 15;
        float4 v = ((const float4*)(query + ((size_t)bh * S + q0 + r) * D))[c];
        ulonglong2 p0, p1;
        p0.x = pack2(v.x * 0.125f); p0.y = pack2(v.y * 0.125f);
        p1.x = pack2(v.z * 0.125f); p1.y = pack2(v.w * 0.125f);
        *(ulonglong2*)&qs2u[r * D + c * 4]     = p0;
        *(ulonglong2*)&qs2u[r * D + c * 4 + 2] = p1;
        float4 L = ((const float4*)(lisrc + ((size_t)bh * S + q0 + r) * D))[c];
        *(float4*)&liin[r * D + c * 4] = L;
    }
#pragma unroll
    for (int u = 0; u < 4; u++)
        ((float4*)peS)[tid + u * 256] = ((const float4*)pe)[tid + u * 256];
    __syncthreads();

    // ---- li tile: li[r][p] = sum_d liin[r][d] * pe[d][p] ---------------------
    {
        const int ox = tid & 31;   // col pair {2ox, 2ox+1}
        const int sy = tid >> 5;   // rows 4sy..4sy+3
        unsigned long long acc2[4];
#pragma unroll
        for (int i = 0; i < 4; i++) acc2[i] = 0ull;
#pragma unroll
        for (int k4 = 0; k4 < 16; k4++) {
            unsigned long long wv[4];
#pragma unroll
            for (int t = 0; t < 4; t++)
                wv[t] = *(const unsigned long long*)&peS[(4 * k4 + t) * 64 + 2 * ox];
#pragma unroll
            for (int i = 0; i < 4; i++) {
                float4 av = *(const float4*)&liin[(4 * sy + i) * D + 4 * k4];
                fma2(acc2[i], pack2(av.x), wv[0]);
                fma2(acc2[i], pack2(av.y), wv[1]);
                fma2(acc2[i], pack2(av.z), wv[2]);
                fma2(acc2[i], pack2(av.w), wv[3]);
            }
        }
        __syncthreads();  // peS/liin reads done before kpT staging overwrites
#pragma unroll
        for (int i = 0; i < 4; i++) {
            float2 u = unpack2(acc2[i]);
            *(float2*)&li[(4 * sy + i) * NPOS + 2 * ox] = u;
        }
    }
    // prologue: stage first chunk into buffer 0
    stage_chunk(kpT, bh, S - KC, tid, key, wk);
    __syncthreads();

    // ---- main backward chunk loop -------------------------------------------
    float carry[4];
#pragma unroll
    for (int i = 0; i < 4; i++) carry[i] = 0.f;
    bool wdone = false;
    int pbuf = 0;

    for (int jc = S - KC; jc >= 0; jc -= KC) {
        float* kbuf = kpT + pbuf * 4096;
        // issue next chunk's staging into the other buffer (no consumer conflict)
        if (jc >= KC)
            stage_chunk(kpT + (pbuf ^ 1) * 4096, bh, jc - KC, tid, key, wk);

        if (!wdone) {
            // GEMM slice: warp rows 4*wrp..+3, lane cols {2*lane, 2*lane+1}
            unsigned long long acc[4];
#pragma unroll
            for (int i = 0; i < 4; i++) acc[i] = 0ull;

#pragma unroll
            for (int d4 = 0; d4 < 16; d4++) {
                unsigned long long kv[4];
#pragma unroll
                for (int t = 0; t < 4; t++)
                    kv[t] = *(const unsigned long long*)&kbuf[(4 * d4 + t) * KC + 2 * lane];
#pragma unroll
                for (int i = 0; i < 4; i++) {
                    const unsigned long long* qrow = qs2u + (4 * wrp + i) * D + 4 * d4;
                    ulonglong2 a01 = *(const ulonglong2*)qrow;
                    ulonglong2 a23 = *(const ulonglong2*)(qrow + 2);
                    fma2(acc[i], a01.x, kv[0]);
                    fma2(acc[i], a01.y, kv[1]);
                    fma2(acc[i], a23.x, kv[2]);
                    fma2(acc[i], a23.y, kv[3]);
                }
            }

            // sigmoid + suffix scan + interp store
            float wm = 1e30f;
#pragma unroll
            for (int i = 0; i < 4; i++) {
                int r = 4 * wrp + i;
                float2 u = unpack2(acc[i]);
                float g0 = __fdividef(1.f, 1.f + __expf(-u.x));
                float g1 = __fdividef(1.f, 1.f + __expf(-u.y));
                float v1 = g1;
                float v0 = g0 + g1;
                float inc = v0;
#pragma unroll
                for (int off = 1; off < 32; off <<= 1) {
                    float n = __shfl_down_sync(0xffffffffu, inc, off);
                    if (lane + off < 32) inc += n;
                }
                float base = carry[i] + (inc - v0);
                const float* lir = &li[r * NPOS];
                float2 o;
                o.x = interp_li(base + v0, lir);
                o.y = interp_li(base + v1, lir);
                *(float2*)(out + ((size_t)bh * S + q0 + r) * S + jc + 2 * lane) = o;
                carry[i] += __shfl_sync(0xffffffffu, inc, 0);
                wm = fminf(wm, carry[i]);
            }

            if (wm >= NPOS_M1) {
                wdone = true;
                // fill remaining cols [0, jc) for this warp's 4 rows
                int nf4 = jc >> 2;
#pragma unroll
                for (int i = 0; i < 4; i++) {
                    int r = 4 * wrp + i;
                    float Lv = li[r * NPOS + 63];
                    float4 o = make_float4(Lv, Lv, Lv, Lv);
                    float4* orow = (float4*)(out + ((size_t)bh * S + q0 + r) * S);
                    for (int c4 = lane; c4 < nf4; c4 += 32) orow[c4] = o;
                }
            }
        }

        // barrier doubles as all-done vote; also publishes next staged chunk
        if (__syncthreads_and((int)wdone)) break;
        pbuf ^= 1;
    }
}

// ---------------------------------------------------------------------------
extern "C" void kernel_launch(void* const* d_in, const int* in_sizes, int n_in,
                              void* d_out, int out_size) {
    const float* query = (const float*)d_in[0];
    const float* key   = (const float*)d_in[2];
    const float* pe    = (const float*)d_in[4];
    const float* wk    = (const float*)d_in[5];
    const int*   flag  = (const int*)d_in[6];
    float* out = (float*)d_out;

    keyproj_kernel<<<dim3(BH, KP_COLS / 64), 256>>>(key, wk);

    cudaFuncSetAttribute(cope_kernel,
                         cudaFuncAttributeMaxDynamicSharedMemorySize, SMEM_BYTES);
    cope_kernel<<<dim3(S / TQ, BH), 256, SMEM_BYTES>>>(query, key, pe, wk, flag, out);
}

// round 6
// speedup vs baseline: 1.1924x; 1.1924x over previous
#include <cuda_runtime.h>
#include <cstdint>

#define S 1024
#define D 64
#define NPOS 64
#define BH 48
#define KC 128
#define TQ 32
#define KP_COLS 256            // precomputed keyproj tail columns
#define KP_START (S - KP_COLS) // 768
#define NPOS_M1 63.0f

// Scratch (allowed: __device__ globals)
__device__ float g_keypT[(size_t)BH * D * S];    // [bh][d][s] (only s >= KP_START filled)

// ---- packed f32x2 helpers ---------------------------------------------------
__device__ __forceinline__ unsigned long long pack2(float a) {
    unsigned long long r;
    asm("mov.b64 %0, {%1, %1};" : "=l"(r) : "f"(a));
    return r;
}
__device__ __forceinline__ void fma2(unsigned long long& d,
                                     unsigned long long a, unsigned long long b) {
    asm("fma.rn.f32x2 %0, %1, %2, %0;" : "+l"(d) : "l"(a), "l"(b));
}
__device__ __forceinline__ float2 unpack2(unsigned long long v) {
    float2 f;
    asm("mov.b64 {%0, %1}, %2;" : "=f"(f.x), "=f"(f.y) : "l"(v));
    return f;
}

// ---------------------------------------------------------------------------
// keyproj tail: g_keypT[bh][d][s] = sum_k key[bh][s][k]*w_k[k][d], s in tail
// ---------------------------------------------------------------------------
__global__ __launch_bounds__(256) void keyproj_kernel(
    const float* __restrict__ key, const float* __restrict__ wk)
{
    __shared__ float w_s[64 * 64];
    __shared__ float in_s[64 * 68];
    const int bh  = blockIdx.x;
    const int s0  = KP_START + blockIdx.y * 64;
    const int tid = threadIdx.x;

    for (int idx = tid; idx < 1024; idx += 256)
        ((float4*)w_s)[idx] = ((const float4*)wk)[idx];
    {
        const float* kp = key + ((size_t)bh * S + s0) * D;
        for (int idx = tid; idx < 64 * 16; idx += 256) {
            int r = idx >> 4, c = idx & 15;
            float4 v = ((const float4*)(kp + (size_t)r * D))[c];
            *(float4*)&in_s[r * 68 + c * 4] = v;
        }
    }
    __syncthreads();

    const int ox = tid & 15;   // d-group
    const int sy = tid >> 4;   // s-group

    unsigned long long acc[4][2];
#pragma unroll
    for (int i = 0; i < 4; i++) { acc[i][0] = 0ull; acc[i][1] = 0ull; }

#pragma unroll
    for (int k4 = 0; k4 < 16; k4++) {
        float4 av[4];
#pragma unroll
        for (int i = 0; i < 4; i++)
            av[i] = *(const float4*)&in_s[(4 * sy + i) * 68 + 4 * k4];
#pragma unroll
        for (int t = 0; t < 4; t++) {
            ulonglong2 wv = *(const ulonglong2*)&w_s[(4 * k4 + t) * 64 + 4 * ox];
#pragma unroll
            for (int i = 0; i < 4; i++) {
                float a = (t == 0) ? av[i].x : (t == 1) ? av[i].y : (t == 2) ? av[i].z : av[i].w;
                unsigned long long a2 = pack2(a);
                fma2(acc[i][0], a2, wv.x);
                fma2(acc[i][1], a2, wv.y);
            }
        }
    }

    float a_[4][4];
#pragma unroll
    for (int i = 0; i < 4; i++) {
        float2 u0 = unpack2(acc[i][0]), u1 = unpack2(acc[i][1]);
        a_[i][0] = u0.x; a_[i][1] = u0.y; a_[i][2] = u1.x; a_[i][3] = u1.y;
    }
#pragma unroll
    for (int j = 0; j < 4; j++) {
        float4 o = make_float4(a_[0][j], a_[1][j], a_[2][j], a_[3][j]);
        *(float4*)&g_keypT[((size_t)bh * D + 4 * ox + j) * S + s0 + 4 * sy] = o;
    }
}

// ---------------------------------------------------------------------------
// Main fused kernel. 128 threads, 4 warps x 8 rows, KC=128, lane = 4 cols.
// smem floats: qs2 dup [32][64] u64 (4096 f) | li [32][64] (2048 f) |
//              kpT [64][128] (8192 f; overlaid by peS[4096]+liin[2048] pre-loop)
// Total 57344 B -> 4 blocks/SM.
// ---------------------------------------------------------------------------
#define QS2_F   0
#define LI_F    4096
#define KPT_F   6144
#define SMEM_FLOATS 14336
#define SMEM_BYTES (SMEM_FLOATS * 4)

__device__ __forceinline__ float interp_li(float pos, const float* __restrict__ lir) {
    pos = fminf(pos, NPOS_M1);
    float pf = floorf(pos);
    int ip = (int)pf;
    float w = pos - pf;
    int ic = (ip < 63) ? ip + 1 : 63;
    float lf = lir[ip], lc = lir[ic];
    return fmaf(w, lc - lf, lf);
}

__device__ __forceinline__ void stage_chunk(
    float* __restrict__ kbuf, int bh, int jc, int tid,
    const float* __restrict__ key, const float* __restrict__ wk)
{
    if (jc >= KP_START) {
        const float* gkp = g_keypT + (size_t)bh * D * S + jc;
#pragma unroll
        for (int u = 0; u < 16; u++) {
            int idx = tid + u * 128;          // 2048 float4
            int d = idx >> 5, c4 = idx & 31;
            float4 v = ((const float4*)(gkp + (size_t)d * S))[c4];
            *(float4*)&kbuf[d * KC + c4 * 4] = v;
        }
    } else {
        // correctness fallback (statistically never taken)
        for (int idx = tid; idx < D * KC; idx += 128) {
            int d = idx >> 7, c = idx & 127;
            const float* krow = key + ((size_t)bh * S + jc + c) * D;
            float s = 0.f;
#pragma unroll
            for (int k = 0; k < D; k++) s += krow[k] * wk[k * D + d];
            kbuf[d * KC + c] = s;
        }
    }
}

__global__ __launch_bounds__(128, 4) void cope_kernel(
    const float* __restrict__ query, const float* __restrict__ key,
    const float* __restrict__ pe, const float* __restrict__ wk,
    const int* __restrict__ flag, float* __restrict__ out)
{
    extern __shared__ float sm[];
    unsigned long long* qs2u = (unsigned long long*)(sm + QS2_F); // [32][64] dup pairs
    float* li   = sm + LI_F;                                      // [32][64]
    float* kpT  = sm + KPT_F;                                     // [64][128]
    float* peS  = sm + KPT_F;                                     // overlay: pe [64][64]
    float* liin = sm + KPT_F + 4096;                              // overlay: [32][64]

    const int bh   = blockIdx.y;
    const int q0   = blockIdx.x * TQ;
    const int tid  = threadIdx.x;
    const int lane = tid & 31;
    const int wrp  = tid >> 5;     // 0..3, owns rows 8*wrp..8*wrp+7

    // ---- register prefetch of chunk 1 (jc = S-KC, always >= KP_START) -------
    float4 pf[16];
    {
        const float* gkp = g_keypT + (size_t)bh * D * S + (S - KC);
#pragma unroll
        for (int u = 0; u < 16; u++) {
            int idx = tid + u * 128;
            int d = idx >> 5, c4 = idx & 31;
            pf[u] = ((const float4*)(gkp + (size_t)d * S))[c4];
        }
    }

    // ---- stage: qs2 (query*0.125 dup), liin, pe ------------------------------
    const float* lisrc = (flag[0] != 0) ? query : key;
#pragma unroll
    for (int u = 0; u < 4; u++) {
        int idx = tid + u * 128;            // 512 float4 groups
        int r = idx >> 4, c = idx & 15;
        float4 v = ((const float4*)(query + ((size_t)bh * S + q0 + r) * D))[c];
        ulonglong2 p0, p1;
        p0.x = pack2(v.x * 0.125f); p0.y = pack2(v.y * 0.125f);
        p1.x = pack2(v.z * 0.125f); p1.y = pack2(v.w * 0.125f);
        *(ulonglong2*)&qs2u[r * D + c * 4]     = p0;
        *(ulonglong2*)&qs2u[r * D + c * 4 + 2] = p1;
        float4 L = ((const float4*)(lisrc + ((size_t)bh * S + q0 + r) * D))[c];
        *(float4*)&liin[r * D + c * 4] = L;
    }
#pragma unroll
    for (int u = 0; u < 8; u++)
        ((float4*)peS)[tid + u * 128] = ((const float4*)pe)[tid + u * 128];
    __syncthreads();

    // ---- li tile: li[r][p] = sum_d liin[r][d] * pe[d][p] ---------------------
    {
        const int ox = tid & 15;   // cols 4ox..4ox+3
        const int sy = tid >> 4;   // rows 4sy..4sy+3 (sy 0..7)
        unsigned long long acc[4][2];
#pragma unroll
        for (int i = 0; i < 4; i++) { acc[i][0] = 0ull; acc[i][1] = 0ull; }
#pragma unroll
        for (int k4 = 0; k4 < 16; k4++) {
            float4 av[4];
#pragma unroll
            for (int i = 0; i < 4; i++)
                av[i] = *(const float4*)&liin[(4 * sy + i) * D + 4 * k4];
#pragma unroll
            for (int t = 0; t < 4; t++) {
                ulonglong2 wv = *(const ulonglong2*)&peS[(4 * k4 + t) * 64 + 4 * ox];
#pragma unroll
                for (int i = 0; i < 4; i++) {
                    float a = (t == 0) ? av[i].x : (t == 1) ? av[i].y : (t == 2) ? av[i].z : av[i].w;
                    unsigned long long a2 = pack2(a);
                    fma2(acc[i][0], a2, wv.x);
                    fma2(acc[i][1], a2, wv.y);
                }
            }
        }
#pragma unroll
        for (int i = 0; i < 4; i++) {
            float2 u0 = unpack2(acc[i][0]), u1 = unpack2(acc[i][1]);
            float4 o = make_float4(u0.x, u0.y, u1.x, u1.y);
            *(float4*)&li[(4 * sy + i) * NPOS + 4 * ox] = o;   // li region separate: safe
        }
    }
    __syncthreads();   // peS/liin reads complete

    // dump prefetched chunk 1 into kpT
#pragma unroll
    for (int u = 0; u < 16; u++) {
        int idx = tid + u * 128;
        int d = idx >> 5, c4 = idx & 31;
        *(float4*)&kpT[d * KC + c4 * 4] = pf[u];
    }
    __syncthreads();

    // ---- main backward chunk loop -------------------------------------------
    float carry[8];
#pragma unroll
    for (int i = 0; i < 8; i++) carry[i] = 0.f;
    bool wdone = false;

    for (int jc = S - KC; ; jc -= KC) {
        if (!wdone) {
            // GEMM: warp rows 8*wrp..+7, lane cols 4*lane..+3
            unsigned long long acc[8][2];
#pragma unroll
            for (int i = 0; i < 8; i++) { acc[i][0] = 0ull; acc[i][1] = 0ull; }

#pragma unroll
            for (int d4 = 0; d4 < 16; d4++) {
                ulonglong2 kv[4];
#pragma unroll
                for (int t = 0; t < 4; t++)
                    kv[t] = *(const ulonglong2*)&kpT[(4 * d4 + t) * KC + 4 * lane];
#pragma unroll
                for (int i = 0; i < 8; i++) {
                    const unsigned long long* qrow = qs2u + (8 * wrp + i) * D + 4 * d4;
                    ulonglong2 a01 = *(const ulonglong2*)qrow;
                    ulonglong2 a23 = *(const ulonglong2*)(qrow + 2);
                    fma2(acc[i][0], a01.x, kv[0].x); fma2(acc[i][1], a01.x, kv[0].y);
                    fma2(acc[i][0], a01.y, kv[1].x); fma2(acc[i][1], a01.y, kv[1].y);
                    fma2(acc[i][0], a23.x, kv[2].x); fma2(acc[i][1], a23.x, kv[2].y);
                    fma2(acc[i][0], a23.y, kv[3].x); fma2(acc[i][1], a23.y, kv[3].y);
                }
            }

            // sigmoid + suffix scan + interpolated store per row
            float wm = 1e30f;
#pragma unroll
            for (int i = 0; i < 8; i++) {
                int r = 8 * wrp + i;
                float2 u0 = unpack2(acc[i][0]), u1 = unpack2(acc[i][1]);
                float g0 = __fdividef(1.f, 1.f + __expf(-u0.x));
                float g1 = __fdividef(1.f, 1.f + __expf(-u0.y));
                float g2 = __fdividef(1.f, 1.f + __expf(-u1.x));
                float g3 = __fdividef(1.f, 1.f + __expf(-u1.y));
                float v3 = g3;
                float v2 = g2 + v3;
                float v1 = g1 + v2;
                float v0 = g0 + v1;
                float inc = v0;
#pragma unroll
                for (int off = 1; off < 32; off <<= 1) {
                    float n = __shfl_down_sync(0xffffffffu, inc, off);
                    if (lane + off < 32) inc += n;
                }
                float base = carry[i] + (inc - v0);
                const float* lir = &li[r * NPOS];
                float4 o;
                o.x = interp_li(base + v0, lir);
                o.y = interp_li(base + v1, lir);
                o.z = interp_li(base + v2, lir);
                o.w = interp_li(base + v3, lir);
                *(float4*)(out + ((size_t)bh * S + q0 + r) * S + jc + 4 * lane) = o;
                carry[i] += __shfl_sync(0xffffffffu, inc, 0);
                wm = fminf(wm, carry[i]);
            }

            if (wm >= NPOS_M1) {
                wdone = true;
                int nf4 = jc >> 2;                 // fill remaining cols [0, jc)
#pragma unroll
                for (int i = 0; i < 8; i++) {
                    int r = 8 * wrp + i;
                    float Lv = li[r * NPOS + 63];
                    float4 o = make_float4(Lv, Lv, Lv, Lv);
                    float4* orow = (float4*)(out + ((size_t)bh * S + q0 + r) * S);
                    for (int c4 = lane; c4 < nf4; c4 += 32) orow[c4] = o;
                }
            }
        }

        bool alldone = __syncthreads_and((int)wdone);
        if (alldone || jc == 0) break;

        stage_chunk(kpT, bh, jc - KC, tid, key, wk);   // lazy: only when needed
        __syncthreads();
    }
}

// ---------------------------------------------------------------------------
extern "C" void kernel_launch(void* const* d_in, const int* in_sizes, int n_in,
                              void* d_out, int out_size) {
    const float* query = (const float*)d_in[0];
    const float* key   = (const float*)d_in[2];
    const float* pe    = (const float*)d_in[4];
    const float* wk    = (const float*)d_in[5];
    const int*   flag  = (const int*)d_in[6];
    float* out = (float*)d_out;

    keyproj_kernel<<<dim3(BH, KP_COLS / 64), 256>>>(key, wk);

    cudaFuncSetAttribute(cope_kernel,
                         cudaFuncAttributeMaxDynamicSharedMemorySize, SMEM_BYTES);
    cope_kernel<<<dim3(S / TQ, BH), 128, SMEM_BYTES>>>(query, key, pe, wk, flag, out);
}